// round 10
// baseline (speedup 1.0000x reference)
#include <cuda_runtime.h>
#include <cuda_bf16.h>
#include <stdint.h>

// out_f32[4096, 4096] = bf16round( x_bf16[4096,4096] @ W_bf16[4096,4096]^T + bias )
// d_out dtype is FLOAT32 (bf16 values widened).
#define TOKENS 4096
#define KDIM   4096
#define NDIM   4096

// 128x128 CTA tile, BK=64, 8 warps (2 m x 4 n), warp tile 64x32.
// 1 CTA/SM (full register budget -> double-buffered fragments), 5-stage pipeline.
#define BM 128
#define BN 128
#define BK 64
#define NUM_KT (KDIM / BK)        // 64
#define STAGES 5
#define A_STAGE 16384             // 128 rows x 128B
#define B_STAGE 16384             // 128 rows x 128B
#define STAGE_BYTES (A_STAGE + B_STAGE)          // 32768
#define SMEM_TOTAL (STAGES * STAGE_BYTES)        // 163840 -> 1 CTA/SM

// Scratch: pre-converted bf16 operands (__device__ globals; no allocs)
__device__ __align__(256) __nv_bfloat16 g_x[(size_t)TOKENS * KDIM];
__device__ __align__(256) __nv_bfloat16 g_w[(size_t)NDIM * KDIM];

// ---------------- helpers ----------------
static __device__ __forceinline__ uint32_t smem_u32(const void* p) {
    uint32_t a;
    asm("{ .reg .u64 t; cvta.to.shared.u64 t, %1; cvt.u32.u64 %0, t; }" : "=r"(a) : "l"(p));
    return a;
}
static __device__ __forceinline__ void cp_async16(uint32_t smem_dst, uint64_t gsrc) {
    asm volatile("cp.async.cg.shared.global [%0], [%1], 16;"
                 :: "r"(smem_dst), "l"(gsrc) : "memory");
}
static __device__ __forceinline__ uint32_t pack_bf162(float a, float b) {
    __nv_bfloat162 p;
    p.x = __float2bfloat16(a); p.y = __float2bfloat16(b);
    return *reinterpret_cast<uint32_t*>(&p);
}

// ---------------- fused conversion kernel ----------------
#define X_U4 ((size_t)TOKENS * KDIM / 8)
#define W_U4 ((size_t)NDIM * KDIM / 8)
__global__ void cvt_all_kernel(const float* __restrict__ x,
                               const float* __restrict__ w,
                               const float* __restrict__ scale) {
    const size_t total = X_U4 + W_U4;
    const size_t stride = (size_t)gridDim.x * blockDim.x;
    const float4* __restrict__ x4 = reinterpret_cast<const float4*>(x);
    const float4* __restrict__ w4 = reinterpret_cast<const float4*>(w);
    uint4* __restrict__ ox = reinterpret_cast<uint4*>(g_x);
    uint4* __restrict__ ow = reinterpret_cast<uint4*>(g_w);
    for (size_t i = (size_t)blockIdx.x * blockDim.x + threadIdx.x; i < total; i += stride) {
        if (i < X_U4) {
            float4 v0 = __ldg(&x4[2 * i]);
            float4 v1 = __ldg(&x4[2 * i + 1]);
            uint4 o;
            o.x = pack_bf162(v0.x, v0.y); o.y = pack_bf162(v0.z, v0.w);
            o.z = pack_bf162(v1.x, v1.y); o.w = pack_bf162(v1.z, v1.w);
            ox[i] = o;
        } else {
            size_t j = i - X_U4;
            int row = (int)(j >> 9);
            // reference: bf16(fp8_val) * bf16(scale) in bf16; fp8 vals exact in
            // f32, so f32 multiply + single bf16 round is identical.
            float s = __bfloat162float(__float2bfloat16(__ldg(&scale[row])));
            float4 v0 = __ldg(&w4[2 * j]);
            float4 v1 = __ldg(&w4[2 * j + 1]);
            uint4 o;
            o.x = pack_bf162(v0.x * s, v0.y * s); o.y = pack_bf162(v0.z * s, v0.w * s);
            o.z = pack_bf162(v1.x * s, v1.y * s); o.w = pack_bf162(v1.z * s, v1.w * s);
            ow[j] = o;
        }
    }
}

// ---------------- mma.sync bf16 GEMM ----------------
__global__ void __launch_bounds__(256, 1)
fp8lin_gemm(const float* __restrict__ bias, float* __restrict__ out) {
    extern __shared__ char smem[];
    const uint32_t sb = smem_u32(smem);
    const int tid = threadIdx.x;
    const int wid = tid >> 5, lane = tid & 31;
    const int wm = wid >> 2, wn = wid & 3;         // 2x4 warp grid, warp tile 64x32
    const int m0 = blockIdx.y * BM, n0 = blockIdx.x * BN;

    uint64_t gA, gB;
    {
        const void* pa = g_x + (size_t)m0 * KDIM;
        const void* pb = g_w + (size_t)n0 * KDIM;
        asm("cvta.to.global.u64 %0, %1;" : "=l"(gA) : "l"(pa));
        asm("cvta.to.global.u64 %0, %1;" : "=l"(gB) : "l"(pb));
    }

    // Stage loader. SMEM rows are 128B, Swizzle<3,4,3>: 16B-chunk ^= (row&7).
    // A: 1024 chunks (4/thread), B: 1024 chunks (4/thread).
    auto load_stage = [&](int s, int kt) {
        const uint32_t sA = sb + (uint32_t)s * STAGE_BYTES;
        const uint32_t sB = sA + A_STAGE;
        const uint64_t koff = (uint64_t)kt * (BK * 2);   // 128B per K-chunk
        #pragma unroll
        for (int it = 0; it < 4; ++it) {
            int idx = tid + it * 256;
            int row = idx >> 3, c = idx & 7;
            uint32_t so = ((uint32_t)row << 7) | (uint32_t)((c << 4) ^ ((row & 7) << 4));
            uint64_t go = (uint64_t)row * (KDIM * 2) + koff + (uint64_t)(c << 4);
            cp_async16(sA + so, gA + go);
            cp_async16(sB + so, gB + go);
        }
        asm volatile("cp.async.commit_group;" ::: "memory");
    };

    // ldmatrix per-thread address components.
    const int j = lane >> 3, i8 = lane & 7;
    // A m16k16 tile mt (4 tiles, rows wm*64 + mt*16):
    // matrices {rows0-7 klo, rows8-15 klo, rows0-7 khi, rows8-15 khi}
    uint32_t aP[4], aX[4];
    #pragma unroll
    for (int mt = 0; mt < 4; ++mt) {
        int r = wm * 64 + mt * 16 + (j & 1) * 8 + i8;
        aP[mt] = (uint32_t)r << 7;
        aX[mt] = (uint32_t)((r & 7) << 4);
    }
    const uint32_t aK = (uint32_t)((j >> 1) << 4);
    // B n16k16 group g (2 groups, rows wn*32 + g*16):
    // matrices {n0-7 klo, n0-7 khi, n8-15 klo, n8-15 khi}
    uint32_t bP[2], bX[2];
    #pragma unroll
    for (int g = 0; g < 2; ++g) {
        int r = wn * 32 + g * 16 + ((j >> 1) & 1) * 8 + i8;
        bP[g] = (uint32_t)r << 7;
        bX[g] = (uint32_t)((r & 7) << 4);
    }
    const uint32_t bK = (uint32_t)((j & 1) << 4);

    // Double-buffered fragments (1 CTA/SM -> register headroom for this).
    uint32_t fa[2][4][4], fb[2][2][4];
    float acc[4][4][4];
    #pragma unroll
    for (int mt = 0; mt < 4; ++mt)
        #pragma unroll
        for (int nt = 0; nt < 4; ++nt)
            #pragma unroll
            for (int q = 0; q < 4; ++q) acc[mt][nt][q] = 0.0f;

    auto load_frags = [&](int buf, uint32_t sA, uint32_t sB, int ks) {
        const uint32_t kb = (uint32_t)(ks << 5);
        #pragma unroll
        for (int mt = 0; mt < 4; ++mt) {
            uint32_t addr = sA + aP[mt] + ((kb + aK) ^ aX[mt]);
            asm volatile("ldmatrix.sync.aligned.m8n8.x4.shared.b16 {%0,%1,%2,%3}, [%4];"
                         : "=r"(fa[buf][mt][0]), "=r"(fa[buf][mt][1]),
                           "=r"(fa[buf][mt][2]), "=r"(fa[buf][mt][3])
                         : "r"(addr));
        }
        #pragma unroll
        for (int g = 0; g < 2; ++g) {
            uint32_t addr = sB + bP[g] + ((kb + bK) ^ bX[g]);
            asm volatile("ldmatrix.sync.aligned.m8n8.x4.shared.b16 {%0,%1,%2,%3}, [%4];"
                         : "=r"(fb[buf][g][0]), "=r"(fb[buf][g][1]),
                           "=r"(fb[buf][g][2]), "=r"(fb[buf][g][3])
                         : "r"(addr));
        }
    };

    load_stage(0, 0);
    load_stage(1, 1);
    load_stage(2, 2);
    load_stage(3, 3);

    int s_comp = 0, s_load = 4;
    for (int kt = 0; kt < NUM_KT; ++kt) {
        // wait until stage kt is complete; in-flight groups = stages kt..kt+3.
        if (kt <= NUM_KT - 4) {
            asm volatile("cp.async.wait_group 3;" ::: "memory");
        } else if (kt == NUM_KT - 3) {
            asm volatile("cp.async.wait_group 2;" ::: "memory");
        } else if (kt == NUM_KT - 2) {
            asm volatile("cp.async.wait_group 1;" ::: "memory");
        } else {
            asm volatile("cp.async.wait_group 0;" ::: "memory");
        }
        // Single barrier: publishes stage kt AND protects stage (kt+4)%5
        // == stage (kt-1)%5 (read finished by all warps at this barrier).
        __syncthreads();
        if (kt + 4 < NUM_KT) {
            load_stage(s_load, kt + 4);
            if (++s_load == STAGES) s_load = 0;
        }

        const uint32_t sA = sb + (uint32_t)s_comp * STAGE_BYTES;
        const uint32_t sB = sA + A_STAGE;
        if (++s_comp == STAGES) s_comp = 0;

        load_frags(0, sA, sB, 0);
        #pragma unroll
        for (int ks = 0; ks < 4; ++ks) {
            const int cur = ks & 1;
            if (ks < 3) load_frags(cur ^ 1, sA, sB, ks + 1);
            #pragma unroll
            for (int mt = 0; mt < 4; ++mt) {
                #pragma unroll
                for (int nt = 0; nt < 4; ++nt) {
                    const uint32_t b0 = fb[cur][nt >> 1][(nt & 1) * 2];
                    const uint32_t b1 = fb[cur][nt >> 1][(nt & 1) * 2 + 1];
                    asm volatile(
                        "mma.sync.aligned.m16n8k16.row.col.f32.bf16.bf16.f32 "
                        "{%0,%1,%2,%3}, {%4,%5,%6,%7}, {%8,%9}, {%0,%1,%2,%3};"
                        : "+f"(acc[mt][nt][0]), "+f"(acc[mt][nt][1]),
                          "+f"(acc[mt][nt][2]), "+f"(acc[mt][nt][3])
                        : "r"(fa[cur][mt][0]), "r"(fa[cur][mt][1]),
                          "r"(fa[cur][mt][2]), "r"(fa[cur][mt][3]),
                          "r"(b0), "r"(b1));
                }
            }
        }
    }

    // ---- epilogue: f32 acc -> bf16 round, + bf16 bias (reference bf16 math),
    // ---- store widened to FLOAT32.
    const int g4 = lane >> 2, tig = lane & 3;
    #pragma unroll
    for (int nt = 0; nt < 4; ++nt) {
        const int col = n0 + wn * 32 + nt * 8 + tig * 2;
        const __nv_bfloat16 bz0 = __float2bfloat16(__ldg(&bias[col]));
        const __nv_bfloat16 bz1 = __float2bfloat16(__ldg(&bias[col + 1]));
        #pragma unroll
        for (int mt = 0; mt < 4; ++mt) {
            const int r0 = m0 + wm * 64 + mt * 16 + g4;
            float2 v0, v1;
            v0.x = __bfloat162float(__hadd(__float2bfloat16(acc[mt][nt][0]), bz0));
            v0.y = __bfloat162float(__hadd(__float2bfloat16(acc[mt][nt][1]), bz1));
            v1.x = __bfloat162float(__hadd(__float2bfloat16(acc[mt][nt][2]), bz0));
            v1.y = __bfloat162float(__hadd(__float2bfloat16(acc[mt][nt][3]), bz1));
            *reinterpret_cast<float2*>(out + (size_t)r0 * NDIM + col) = v0;
            *reinterpret_cast<float2*>(out + (size_t)(r0 + 8) * NDIM + col) = v1;
        }
    }
}

// ---------------- launch ----------------
extern "C" void kernel_launch(void* const* d_in, const int* in_sizes, int n_in,
                              void* d_out, int out_size) {
    const float* x     = (const float*)d_in[0];   // [2,2048,4096] f32
    const float* w     = (const float*)d_in[1];   // [4096,4096] f32 (fp8-representable)
    const float* scale = (const float*)d_in[2];   // [4096,1] f32
    const float* bias  = (const float*)d_in[3];   // [4096] f32
    float* out         = (float*)d_out;           // [2,2048,4096] f32 (bf16 values widened)

    cudaFuncSetAttribute(fp8lin_gemm, cudaFuncAttributeMaxDynamicSharedMemorySize, SMEM_TOTAL);

    cvt_all_kernel<<<4096, 256>>>(x, w, scale);

    dim3 grid(NDIM / BN, TOKENS / BM);  // (32, 32) = 1024 CTAs
    fp8lin_gemm<<<grid, 256, SMEM_TOTAL>>>(bias, out);
}

// round 11
// speedup vs baseline: 1.1470x; 1.1470x over previous
#include <cuda_runtime.h>
#include <cuda_bf16.h>
#include <stdint.h>

// out_f32[4096, 4096] = bf16round( x_bf16[4096,4096] @ W_bf16[4096,4096]^T + bias )
// d_out dtype is FLOAT32 (bf16 values widened).
#define TOKENS 4096
#define KDIM   4096
#define NDIM   4096

// R8-optimal config: 128x128 CTA tile, BK=64, 8 warps (4m x 2n), warp tile 32x64,
// 3 stages, 2 CTA/SM. New: persistent CTAs + flat cross-tile chunk pipeline +
// single barrier per K-iter.
#define BM 128
#define BN 128
#define BK 64
#define KT_PER_TILE (KDIM / BK)       // 64
#define N_TILES ((TOKENS / BM) * (NDIM / BN))   // 1024
#define GRID_P 304                    // 2 per SM on 152 SMs
#define STAGES 3
#define A_STAGE 16384                 // 128 rows x 128B
#define STAGE_BYTES 32768             // A 16K + B 16K
#define SMEM_TOTAL (STAGES * STAGE_BYTES)   // 98304 -> 2 CTAs/SM

// Scratch: pre-converted bf16 operands (__device__ globals; no allocs)
__device__ __align__(256) __nv_bfloat16 g_x[(size_t)TOKENS * KDIM];
__device__ __align__(256) __nv_bfloat16 g_w[(size_t)NDIM * KDIM];

// ---------------- helpers ----------------
static __device__ __forceinline__ uint32_t smem_u32(const void* p) {
    uint32_t a;
    asm("{ .reg .u64 t; cvta.to.shared.u64 t, %1; cvt.u32.u64 %0, t; }" : "=r"(a) : "l"(p));
    return a;
}
static __device__ __forceinline__ void cp_async16(uint32_t smem_dst, uint64_t gsrc) {
    asm volatile("cp.async.cg.shared.global [%0], [%1], 16;"
                 :: "r"(smem_dst), "l"(gsrc) : "memory");
}
static __device__ __forceinline__ uint32_t pack_bf162(float a, float b) {
    __nv_bfloat162 p;
    p.x = __float2bfloat16(a); p.y = __float2bfloat16(b);
    return *reinterpret_cast<uint32_t*>(&p);
}

// ---------------- fused conversion kernel ----------------
#define X_U4 ((size_t)TOKENS * KDIM / 8)
#define W_U4 ((size_t)NDIM * KDIM / 8)
__global__ void cvt_all_kernel(const float* __restrict__ x,
                               const float* __restrict__ w,
                               const float* __restrict__ scale) {
    const size_t total = X_U4 + W_U4;
    const size_t stride = (size_t)gridDim.x * blockDim.x;
    const float4* __restrict__ x4 = reinterpret_cast<const float4*>(x);
    const float4* __restrict__ w4 = reinterpret_cast<const float4*>(w);
    uint4* __restrict__ ox = reinterpret_cast<uint4*>(g_x);
    uint4* __restrict__ ow = reinterpret_cast<uint4*>(g_w);
    for (size_t i = (size_t)blockIdx.x * blockDim.x + threadIdx.x; i < total; i += stride) {
        if (i < X_U4) {
            float4 v0 = __ldg(&x4[2 * i]);
            float4 v1 = __ldg(&x4[2 * i + 1]);
            uint4 o;
            o.x = pack_bf162(v0.x, v0.y); o.y = pack_bf162(v0.z, v0.w);
            o.z = pack_bf162(v1.x, v1.y); o.w = pack_bf162(v1.z, v1.w);
            ox[i] = o;
        } else {
            size_t j = i - X_U4;
            int row = (int)(j >> 9);
            // reference: bf16(fp8_val) * bf16(scale) in bf16; fp8 vals exact in
            // f32, so f32 multiply + single bf16 round is identical.
            float s = __bfloat162float(__float2bfloat16(__ldg(&scale[row])));
            float4 v0 = __ldg(&w4[2 * j]);
            float4 v1 = __ldg(&w4[2 * j + 1]);
            uint4 o;
            o.x = pack_bf162(v0.x * s, v0.y * s); o.y = pack_bf162(v0.z * s, v0.w * s);
            o.z = pack_bf162(v1.x * s, v1.y * s); o.w = pack_bf162(v1.z * s, v1.w * s);
            ow[j] = o;
        }
    }
}

// ---------------- persistent mma.sync bf16 GEMM ----------------
__global__ void __launch_bounds__(256, 2)
fp8lin_gemm(const float* __restrict__ bias, float* __restrict__ out) {
    extern __shared__ char smem[];
    const uint32_t sb = smem_u32(smem);
    const int tid = threadIdx.x;
    const int wid = tid >> 5, lane = tid & 31;
    const int wm = wid >> 1, wn = wid & 1;         // 4x2 warp grid, warp tile 32x64
    const int bid = blockIdx.x;

    uint64_t baseA, baseB;
    {
        const void* pa = g_x;
        const void* pb = g_w;
        asm("cvta.to.global.u64 %0, %1;" : "=l"(baseA) : "l"(pa));
        asm("cvta.to.global.u64 %0, %1;" : "=l"(baseB) : "l"(pb));
    }

    // tiles for this CTA: t = bid + j*GRID_P, j = 0..ntiles-1
    const int ntiles = (N_TILES - 1 - bid) / GRID_P + 1;
    const int total_chunks = ntiles * KT_PER_TILE;

    // Issue cp.async for flat chunk index c (tile j = c>>6, kt = c&63).
    // Each tile's A panel = 1 MB at baseA + tm<<20; B panel at baseB + tn<<20.
    // SMEM rows 128B, Swizzle<3,4,3>: 16B-chunk ^= (row&7).
    auto load_chunk = [&](int c) {
        const int t = bid + (c >> 6) * GRID_P;
        const int kt = c & 63;
        const uint64_t gA = baseA + ((uint64_t)(t >> 5) << 20);
        const uint64_t gB = baseB + ((uint64_t)(t & 31) << 20);
        const int s = c % STAGES;
        const uint32_t sA = sb + (uint32_t)s * STAGE_BYTES;
        const uint32_t sB = sA + A_STAGE;
        const uint64_t koff = (uint64_t)kt * (BK * 2);   // 128B per K-chunk
        #pragma unroll
        for (int it = 0; it < 4; ++it) {
            int idx = tid + it * 256;
            int row = idx >> 3, ch = idx & 7;
            uint32_t so = ((uint32_t)row << 7) | (uint32_t)((ch << 4) ^ ((row & 7) << 4));
            uint64_t go = (uint64_t)row * (KDIM * 2) + koff + (uint64_t)(ch << 4);
            cp_async16(sA + so, gA + go);
            cp_async16(sB + so, gB + go);
        }
        asm volatile("cp.async.commit_group;" ::: "memory");
    };

    // ldmatrix per-thread address components.
    const int j8 = lane >> 3, i8 = lane & 7;
    // A m16k16 tile mt: matrices {rows0-7 klo, rows8-15 klo, rows0-7 khi, rows8-15 khi}
    uint32_t aP[2], aX[2];
    #pragma unroll
    for (int mt = 0; mt < 2; ++mt) {
        int r = wm * 32 + mt * 16 + (j8 & 1) * 8 + i8;
        aP[mt] = (uint32_t)r << 7;
        aX[mt] = (uint32_t)((r & 7) << 4);
    }
    const uint32_t aK = (uint32_t)((j8 >> 1) << 4);
    // B n16k16 group g: matrices {n0-7 klo, n0-7 khi, n8-15 klo, n8-15 khi}
    uint32_t bP[4], bX[4];
    #pragma unroll
    for (int g = 0; g < 4; ++g) {
        int r = wn * 64 + g * 16 + ((j8 >> 1) & 1) * 8 + i8;
        bP[g] = (uint32_t)r << 7;
        bX[g] = (uint32_t)((r & 7) << 4);
    }
    const uint32_t bK = (uint32_t)((j8 & 1) << 4);

    float acc[2][8][4];
    #pragma unroll
    for (int mt = 0; mt < 2; ++mt)
        #pragma unroll
        for (int nt = 0; nt < 8; ++nt)
            #pragma unroll
            for (int q = 0; q < 4; ++q) acc[mt][nt][q] = 0.0f;

    const int g4 = lane >> 2, tig = lane & 3;

    load_chunk(0);
    load_chunk(1);

    #pragma unroll 1
    for (int c = 0; c < total_chunks; ++c) {
        // Before wait: committed groups are 0..c+1; wait_group 1 -> group c done.
        // Final iter has nothing in flight beyond c -> wait_group 0.
        if (c + 1 < total_chunks) {
            asm volatile("cp.async.wait_group 1;" ::: "memory");
        } else {
            asm volatile("cp.async.wait_group 0;" ::: "memory");
        }
        // Single barrier: publishes chunk c's SMEM to all warps AND proves all
        // warps finished reading stage (c-1)%3 == stage (c+2)%3 written below.
        __syncthreads();
        if (c + 2 < total_chunks) load_chunk(c + 2);

        const int s = c % STAGES;
        const uint32_t sA = sb + (uint32_t)s * STAGE_BYTES;
        const uint32_t sB = sA + A_STAGE;

        #pragma unroll
        for (int ks = 0; ks < 4; ++ks) {
            const uint32_t kb = (uint32_t)(ks << 5);
            uint32_t a[2][4], b[4][4];
            #pragma unroll
            for (int mt = 0; mt < 2; ++mt) {
                uint32_t addr = sA + aP[mt] + ((kb + aK) ^ aX[mt]);
                asm volatile("ldmatrix.sync.aligned.m8n8.x4.shared.b16 {%0,%1,%2,%3}, [%4];"
                             : "=r"(a[mt][0]), "=r"(a[mt][1]), "=r"(a[mt][2]), "=r"(a[mt][3])
                             : "r"(addr));
            }
            #pragma unroll
            for (int g = 0; g < 4; ++g) {
                uint32_t addr = sB + bP[g] + ((kb + bK) ^ bX[g]);
                asm volatile("ldmatrix.sync.aligned.m8n8.x4.shared.b16 {%0,%1,%2,%3}, [%4];"
                             : "=r"(b[g][0]), "=r"(b[g][1]), "=r"(b[g][2]), "=r"(b[g][3])
                             : "r"(addr));
            }
            #pragma unroll
            for (int mt = 0; mt < 2; ++mt) {
                #pragma unroll
                for (int nt = 0; nt < 8; ++nt) {
                    const uint32_t b0 = b[nt >> 1][(nt & 1) * 2];
                    const uint32_t b1 = b[nt >> 1][(nt & 1) * 2 + 1];
                    asm volatile(
                        "mma.sync.aligned.m16n8k16.row.col.f32.bf16.bf16.f32 "
                        "{%0,%1,%2,%3}, {%4,%5,%6,%7}, {%8,%9}, {%0,%1,%2,%3};"
                        : "+f"(acc[mt][nt][0]), "+f"(acc[mt][nt][1]),
                          "+f"(acc[mt][nt][2]), "+f"(acc[mt][nt][3])
                        : "r"(a[mt][0]), "r"(a[mt][1]), "r"(a[mt][2]), "r"(a[mt][3]),
                          "r"(b0), "r"(b1));
                }
            }
        }

        // ---- tile boundary: epilogue (registers + gmem only; no SMEM, no
        // barrier). cp.async for next tile's chunks stays in flight underneath.
        if ((c & 63) == 63) {
            const int t = bid + (c >> 6) * GRID_P;
            const int m0 = (t >> 5) * BM, n0 = (t & 31) * BN;
            #pragma unroll
            for (int nt = 0; nt < 8; ++nt) {
                const int col = n0 + wn * 64 + nt * 8 + tig * 2;
                const __nv_bfloat16 bz0 = __float2bfloat16(__ldg(&bias[col]));
                const __nv_bfloat16 bz1 = __float2bfloat16(__ldg(&bias[col + 1]));
                #pragma unroll
                for (int mt = 0; mt < 2; ++mt) {
                    const int r0 = m0 + wm * 32 + mt * 16 + g4;
                    float2 v0, v1;
                    v0.x = __bfloat162float(__hadd(__float2bfloat16(acc[mt][nt][0]), bz0));
                    v0.y = __bfloat162float(__hadd(__float2bfloat16(acc[mt][nt][1]), bz1));
                    v1.x = __bfloat162float(__hadd(__float2bfloat16(acc[mt][nt][2]), bz0));
                    v1.y = __bfloat162float(__hadd(__float2bfloat16(acc[mt][nt][3]), bz1));
                    *reinterpret_cast<float2*>(out + (size_t)r0 * NDIM + col) = v0;
                    *reinterpret_cast<float2*>(out + (size_t)(r0 + 8) * NDIM + col) = v1;
                    acc[mt][nt][0] = 0.0f; acc[mt][nt][1] = 0.0f;
                    acc[mt][nt][2] = 0.0f; acc[mt][nt][3] = 0.0f;
                }
            }
        }
    }
}

// ---------------- launch ----------------
extern "C" void kernel_launch(void* const* d_in, const int* in_sizes, int n_in,
                              void* d_out, int out_size) {
    const float* x     = (const float*)d_in[0];   // [2,2048,4096] f32
    const float* w     = (const float*)d_in[1];   // [4096,4096] f32 (fp8-representable)
    const float* scale = (const float*)d_in[2];   // [4096,1] f32
    const float* bias  = (const float*)d_in[3];   // [4096] f32
    float* out         = (float*)d_out;           // [2,2048,4096] f32 (bf16 values widened)

    cudaFuncSetAttribute(fp8lin_gemm, cudaFuncAttributeMaxDynamicSharedMemorySize, SMEM_TOTAL);

    cvt_all_kernel<<<4096, 256>>>(x, w, scale);

    fp8lin_gemm<<<GRID_P, 256, SMEM_TOTAL>>>(bias, out);
}